// round 2
// baseline (speedup 1.0000x reference)
#include <cuda_runtime.h>
#include <cstdint>

#define N_NODES 100000
#define D_IN    512
#define D_OUT   128
#define N_EDGES 640000

// Scratch for h = X @ W  (51.2 MB, static device array: allocation-free)
__device__ __align__(16) float g_h[(size_t)N_NODES * D_OUT];

// ---------------------------------------------------------------------------
// Kernel 1: out[n, j] = bias[j]   (d_out is poisoned; atomics accumulate on top)
// ---------------------------------------------------------------------------
__global__ void init_out_kernel(float* __restrict__ out, const float* __restrict__ bias) {
    const float4* b4 = (const float4*)bias;           // 32 float4 per row
    float4* o4 = (float4*)out;
    int total = N_NODES * D_OUT / 4;                  // 3.2M float4
    for (int i = blockIdx.x * blockDim.x + threadIdx.x; i < total;
         i += gridDim.x * blockDim.x) {
        o4[i] = b4[i & 31];
    }
}

// ---------------------------------------------------------------------------
// Kernel 2: TF32 tensor-core GEMM  g_h = X @ W
// Tiles: BM=128, BN=128 (=D_OUT), BK=32. 256 threads = 8 warps (2x4),
// warp tile 64x32 via m16n8k8 tf32 mma.sync.
// ---------------------------------------------------------------------------
__device__ __forceinline__ uint32_t f2tf32(float f) {
    uint32_t u;
    asm("cvt.rna.tf32.f32 %0, %1;" : "=r"(u) : "f"(f));
    return u;
}

__device__ __forceinline__ void mma_tf32(float c[4], const uint32_t a[4], const uint32_t b[2]) {
    asm volatile(
        "mma.sync.aligned.m16n8k8.row.col.f32.tf32.tf32.f32 "
        "{%0,%1,%2,%3}, {%4,%5,%6,%7}, {%8,%9}, {%0,%1,%2,%3};"
        : "+f"(c[0]), "+f"(c[1]), "+f"(c[2]), "+f"(c[3])
        : "r"(a[0]), "r"(a[1]), "r"(a[2]), "r"(a[3]), "r"(b[0]), "r"(b[1]));
}

#define BM 128
#define BK 32

__global__ __launch_bounds__(256, 2)
void gemm_tf32_kernel(const float* __restrict__ A,   // [N_NODES, 512]
                      const float* __restrict__ B) { // [512, 128]
    __shared__ uint32_t As[BM][36];   // pad 36: conflict-free frag loads
    __shared__ uint32_t Bs[BK][136];  // pad 136: conflict-free frag loads

    const int tid  = threadIdx.x;
    const int warp = tid >> 5;
    const int lane = tid & 31;
    const int wm = (warp >> 2) * 64;  // warp row offset in tile (0 or 64)
    const int wn = (warp & 3) * 32;   // warp col offset (0,32,64,96)
    const int blockRow = blockIdx.x * BM;

    float acc[4][4][4];
#pragma unroll
    for (int mi = 0; mi < 4; mi++)
#pragma unroll
        for (int ni = 0; ni < 4; ni++)
#pragma unroll
            for (int k = 0; k < 4; k++) acc[mi][ni][k] = 0.0f;

    for (int k0 = 0; k0 < D_IN; k0 += BK) {
        // Load A tile 128x32 (1024 float4, 4 per thread)
#pragma unroll
        for (int it = 0; it < 4; ++it) {
            int r  = (tid >> 3) + it * 32;
            int c4 = tid & 7;
            int grow = blockRow + r;
            float4 v = make_float4(0.f, 0.f, 0.f, 0.f);
            if (grow < N_NODES)
                v = *(const float4*)(A + (size_t)grow * D_IN + k0 + c4 * 4);
            As[r][c4 * 4 + 0] = f2tf32(v.x);
            As[r][c4 * 4 + 1] = f2tf32(v.y);
            As[r][c4 * 4 + 2] = f2tf32(v.z);
            As[r][c4 * 4 + 3] = f2tf32(v.w);
        }
        // Load B tile 32x128 (1024 float4, 4 per thread)
#pragma unroll
        for (int it = 0; it < 4; ++it) {
            int kk = (tid >> 5) + it * 8;
            int n4 = tid & 31;
            float4 v = *(const float4*)(B + (size_t)(k0 + kk) * D_OUT + n4 * 4);
            Bs[kk][n4 * 4 + 0] = f2tf32(v.x);
            Bs[kk][n4 * 4 + 1] = f2tf32(v.y);
            Bs[kk][n4 * 4 + 2] = f2tf32(v.z);
            Bs[kk][n4 * 4 + 3] = f2tf32(v.w);
        }
        __syncthreads();

#pragma unroll
        for (int ks = 0; ks < BK; ks += 8) {
            uint32_t afrag[4][4];
#pragma unroll
            for (int mi = 0; mi < 4; mi++) {
                int r = wm + mi * 16 + (lane >> 2);
                int c = ks + (lane & 3);
                afrag[mi][0] = As[r][c];
                afrag[mi][1] = As[r + 8][c];
                afrag[mi][2] = As[r][c + 4];
                afrag[mi][3] = As[r + 8][c + 4];
            }
            uint32_t bfrag[4][2];
#pragma unroll
            for (int ni = 0; ni < 4; ni++) {
                int c = wn + ni * 8 + (lane >> 2);
                bfrag[ni][0] = Bs[ks + (lane & 3)][c];
                bfrag[ni][1] = Bs[ks + (lane & 3) + 4][c];
            }
#pragma unroll
            for (int mi = 0; mi < 4; mi++)
#pragma unroll
                for (int ni = 0; ni < 4; ni++)
                    mma_tf32(acc[mi][ni], afrag[mi], bfrag[ni]);
        }
        __syncthreads();
    }

    // Store accumulators to g_h
#pragma unroll
    for (int mi = 0; mi < 4; mi++) {
#pragma unroll
        for (int ni = 0; ni < 4; ni++) {
            int r0 = blockRow + wm + mi * 16 + (lane >> 2);
            int c0 = wn + ni * 8 + (lane & 3) * 2;
            if (r0 < N_NODES) {
                g_h[(size_t)r0 * D_OUT + c0]     = acc[mi][ni][0];
                g_h[(size_t)r0 * D_OUT + c0 + 1] = acc[mi][ni][1];
            }
            if (r0 + 8 < N_NODES) {
                g_h[(size_t)(r0 + 8) * D_OUT + c0]     = acc[mi][ni][2];
                g_h[(size_t)(r0 + 8) * D_OUT + c0 + 1] = acc[mi][ni][3];
            }
        }
    }
}

// ---------------------------------------------------------------------------
// Kernel 3: edge scatter. One warp per edge; each lane handles one float4
// (128 floats / 32 lanes). Vector reduction red.global.add.v4.f32 (sm_90+)
// => 32 red ops per edge instead of 128 scalar atomics.
// NOTE: edge indices are int32 (JAX x64 disabled downgrades int64 -> int32).
// ---------------------------------------------------------------------------
__global__ void scatter_kernel(const int* __restrict__ src,
                               const int* __restrict__ dst,
                               const float* __restrict__ ew,
                               float* __restrict__ out) {
    const int lane = threadIdx.x & 31;
    int warpId = (blockIdx.x * blockDim.x + threadIdx.x) >> 5;
    const int nWarps = (gridDim.x * blockDim.x) >> 5;

    for (int e = warpId; e < N_EDGES; e += nWarps) {
        const int s = src[e];
        const int d = dst[e];
        const float w = ew[e];
        float4 v = *(const float4*)(g_h + (size_t)s * D_OUT + lane * 4);
        v.x *= w; v.y *= w; v.z *= w; v.w *= w;
        float* p = out + (size_t)d * D_OUT + lane * 4;
        asm volatile("red.global.add.v4.f32 [%0], {%1,%2,%3,%4};"
                     :: "l"(p), "f"(v.x), "f"(v.y), "f"(v.z), "f"(v.w)
                     : "memory");
    }
}

// ---------------------------------------------------------------------------
extern "C" void kernel_launch(void* const* d_in, const int* in_sizes, int n_in,
                              void* d_out, int out_size) {
    const float* features = (const float*)d_in[0];  // [100000, 512] f32
    const int*   edge_src = (const int*)d_in[1];    // [640000] int32 (JAX x64 off)
    const int*   edge_dst = (const int*)d_in[2];    // [640000] int32
    const float* edge_w   = (const float*)d_in[3];  // [640000] f32
    const float* weights  = (const float*)d_in[4];  // [512, 128] f32
    const float* bias     = (const float*)d_in[5];  // [128] f32
    float* out = (float*)d_out;                     // [100000, 128] f32

    (void)in_sizes; (void)n_in; (void)out_size;

    // 1) out = bias (broadcast)
    init_out_kernel<<<2048, 256>>>(out, bias);

    // 2) g_h = features @ weights  (TF32 tensor cores)
    const int gemm_blocks = (N_NODES + BM - 1) / BM;  // 782
    gemm_tf32_kernel<<<gemm_blocks, 256>>>(features, weights);

    // 3) out[dst] += w * g_h[src]  (vector L2 reductions)
    scatter_kernel<<<N_EDGES / 8, 256>>>(edge_src, edge_dst, edge_w, out);
}

// round 3
// speedup vs baseline: 1.2760x; 1.2760x over previous
#include <cuda_runtime.h>
#include <cstdint>

#define N_NODES 100000
#define D_IN    512
#define D_OUT   128
#define N_EDGES 640000

#define BM 128
#define BK 32
#define A_STRIDE 36     // conflict-free A frag loads
#define B_STRIDE 136    // conflict-free B frag loads
#define A_STAGE (BM * A_STRIDE)            // 4608 floats
#define B_STAGE (BK * B_STRIDE)            // 4352 floats
#define SMEM_FLOATS (2 * A_STAGE + 2 * B_STAGE)   // 17920
#define SMEM_BYTES  (SMEM_FLOATS * 4)             // 71680

// Scratch for h = X @ W  (51.2 MB, static device array: allocation-free)
__device__ __align__(16) float g_h[(size_t)N_NODES * D_OUT];

__device__ __forceinline__ uint32_t f2tf32(float f) {
    uint32_t u;
    asm("cvt.rna.tf32.f32 %0, %1;" : "=r"(u) : "f"(f));
    return u;
}

__device__ __forceinline__ void mma_tf32(float c[4], const uint32_t a[4], const uint32_t b[2]) {
    asm volatile(
        "mma.sync.aligned.m16n8k8.row.col.f32.tf32.tf32.f32 "
        "{%0,%1,%2,%3}, {%4,%5,%6,%7}, {%8,%9}, {%0,%1,%2,%3};"
        : "+f"(c[0]), "+f"(c[1]), "+f"(c[2]), "+f"(c[3])
        : "r"(a[0]), "r"(a[1]), "r"(a[2]), "r"(a[3]), "r"(b[0]), "r"(b[1]));
}

__device__ __forceinline__ void cp16(uint32_t saddr, const void* g) {
    asm volatile("cp.async.cg.shared.global [%0], [%1], 16;" :: "r"(saddr), "l"(g));
}

// ---------------------------------------------------------------------------
// Kernel 1: fused [out = bias broadcast] + [g_h = X @ W] (TF32, cp.async 2-stage)
// ---------------------------------------------------------------------------
__global__ __launch_bounds__(256, 2)
void gemm_tf32_kernel(const float* __restrict__ A,    // [N_NODES, 512]
                      const float* __restrict__ B,    // [512, 128]
                      const float* __restrict__ bias, // [128]
                      float* __restrict__ out) {      // [N_NODES, 128]
    extern __shared__ float sm[];
    float* As = sm;                  // [2][BM][A_STRIDE]
    float* Bs = sm + 2 * A_STAGE;    // [2][BK][B_STRIDE]

    const int tid  = threadIdx.x;
    const int warp = tid >> 5;
    const int lane = tid & 31;
    const int wm = (warp >> 2) * 64;
    const int wn = (warp & 3) * 32;
    const int blockRow = blockIdx.x * BM;

    // ---- Fused bias-init of this block's output rows (overlaps with loads) ----
    {
        float4 bv = ((const float4*)bias)[lane];
#pragma unroll
        for (int r = warp; r < BM; r += 8) {
            int grow = blockRow + r;
            if (grow < N_NODES)
                ((float4*)out)[(size_t)grow * 32 + lane] = bv;
        }
    }

    // ---- Prologue: issue stage 0 ----
    {
#pragma unroll
        for (int i = 0; i < 4; i++) {
            int r = (tid >> 3) + i * 32, c4 = tid & 7;
            int grow = blockRow + r; if (grow >= N_NODES) grow = N_NODES - 1;
            uint32_t sa = (uint32_t)__cvta_generic_to_shared(&As[r * A_STRIDE + c4 * 4]);
            cp16(sa, A + (size_t)grow * D_IN + 0 + c4 * 4);
        }
#pragma unroll
        for (int i = 0; i < 4; i++) {
            int kk = (tid >> 5) + i * 8, n4 = tid & 31;
            uint32_t sb = (uint32_t)__cvta_generic_to_shared(&Bs[kk * B_STRIDE + n4 * 4]);
            cp16(sb, B + (size_t)(0 + kk) * D_OUT + n4 * 4);
        }
        asm volatile("cp.async.commit_group;");
    }

    float acc[4][4][4] = {};

    const int NIT = D_IN / BK;  // 16
    for (int it = 0; it < NIT; ++it) {
        // Prefetch next stage (buffer computed in it-1; bottom sync of it-1 protects it)
        if (it + 1 < NIT) {
            const int st = (it + 1) & 1;
            const int k0 = (it + 1) * BK;
#pragma unroll
            for (int i = 0; i < 4; i++) {
                int r = (tid >> 3) + i * 32, c4 = tid & 7;
                int grow = blockRow + r; if (grow >= N_NODES) grow = N_NODES - 1;
                uint32_t sa = (uint32_t)__cvta_generic_to_shared(
                    &As[st * A_STAGE + r * A_STRIDE + c4 * 4]);
                cp16(sa, A + (size_t)grow * D_IN + k0 + c4 * 4);
            }
#pragma unroll
            for (int i = 0; i < 4; i++) {
                int kk = (tid >> 5) + i * 8, n4 = tid & 31;
                uint32_t sb = (uint32_t)__cvta_generic_to_shared(
                    &Bs[st * B_STAGE + kk * B_STRIDE + n4 * 4]);
                cp16(sb, B + (size_t)(k0 + kk) * D_OUT + n4 * 4);
            }
            asm volatile("cp.async.commit_group;");
            asm volatile("cp.async.wait_group 1;");
        } else {
            asm volatile("cp.async.wait_group 0;");
        }
        __syncthreads();

        const float* Asb = As + (it & 1) * A_STAGE;
        const float* Bsb = Bs + (it & 1) * B_STAGE;

#pragma unroll
        for (int ks = 0; ks < BK; ks += 8) {
            uint32_t afrag[4][4], bfrag[4][2];
#pragma unroll
            for (int mi = 0; mi < 4; mi++) {
                int r = wm + mi * 16 + (lane >> 2);
                int c = ks + (lane & 3);
                afrag[mi][0] = f2tf32(Asb[r * A_STRIDE + c]);
                afrag[mi][1] = f2tf32(Asb[(r + 8) * A_STRIDE + c]);
                afrag[mi][2] = f2tf32(Asb[r * A_STRIDE + c + 4]);
                afrag[mi][3] = f2tf32(Asb[(r + 8) * A_STRIDE + c + 4]);
            }
#pragma unroll
            for (int ni = 0; ni < 4; ni++) {
                int c = wn + ni * 8 + (lane >> 2);
                bfrag[ni][0] = f2tf32(Bsb[(ks + (lane & 3)) * B_STRIDE + c]);
                bfrag[ni][1] = f2tf32(Bsb[(ks + (lane & 3) + 4) * B_STRIDE + c]);
            }
#pragma unroll
            for (int mi = 0; mi < 4; mi++)
#pragma unroll
                for (int ni = 0; ni < 4; ni++)
                    mma_tf32(acc[mi][ni], afrag[mi], bfrag[ni]);
        }
        __syncthreads();
    }

    // ---- Store accumulators to g_h ----
#pragma unroll
    for (int mi = 0; mi < 4; mi++) {
#pragma unroll
        for (int ni = 0; ni < 4; ni++) {
            int r0 = blockRow + wm + mi * 16 + (lane >> 2);
            int c0 = wn + ni * 8 + (lane & 3) * 2;
            if (r0 < N_NODES) {
                g_h[(size_t)r0 * D_OUT + c0]     = acc[mi][ni][0];
                g_h[(size_t)r0 * D_OUT + c0 + 1] = acc[mi][ni][1];
            }
            if (r0 + 8 < N_NODES) {
                g_h[(size_t)(r0 + 8) * D_OUT + c0]     = acc[mi][ni][2];
                g_h[(size_t)(r0 + 8) * D_OUT + c0 + 1] = acc[mi][ni][3];
            }
        }
    }
}

// ---------------------------------------------------------------------------
// Kernel 2: warp-batched edge scatter.
// Each warp owns 32 consecutive edges: indices loaded coalesced (one 128B
// transaction each for src/dst/w), broadcast via shfl; all 32 lanes then
// cooperate on each edge (one float4 gather + one red.v4 per lane).
// ---------------------------------------------------------------------------
__global__ void scatter_kernel(const int* __restrict__ src,
                               const int* __restrict__ dst,
                               const float* __restrict__ ew,
                               float* __restrict__ out) {
    const int lane = threadIdx.x & 31;
    const int w = (blockIdx.x * blockDim.x + threadIdx.x) >> 5;
    const int base = w * 32;
    if (base >= N_EDGES) return;

    const int   s  = src[base + lane];
    const int   d  = dst[base + lane];
    const float wt = ew[base + lane];

#pragma unroll 4
    for (int i = 0; i < 32; i++) {
        int   si = __shfl_sync(0xffffffffu, s,  i);
        int   di = __shfl_sync(0xffffffffu, d,  i);
        float wi = __shfl_sync(0xffffffffu, wt, i);
        float4 v = __ldg((const float4*)(g_h + (size_t)si * D_OUT) + lane);
        v.x *= wi; v.y *= wi; v.z *= wi; v.w *= wi;
        float* p = out + (size_t)di * D_OUT + lane * 4;
        asm volatile("red.global.add.v4.f32 [%0], {%1,%2,%3,%4};"
                     :: "l"(p), "f"(v.x), "f"(v.y), "f"(v.z), "f"(v.w)
                     : "memory");
    }
}

// ---------------------------------------------------------------------------
extern "C" void kernel_launch(void* const* d_in, const int* in_sizes, int n_in,
                              void* d_out, int out_size) {
    const float* features = (const float*)d_in[0];  // [100000, 512] f32
    const int*   edge_src = (const int*)d_in[1];    // [640000] int32 (JAX x64 off)
    const int*   edge_dst = (const int*)d_in[2];    // [640000] int32
    const float* edge_w   = (const float*)d_in[3];  // [640000] f32
    const float* weights  = (const float*)d_in[4];  // [512, 128] f32
    const float* bias     = (const float*)d_in[5];  // [128] f32
    float* out = (float*)d_out;                     // [100000, 128] f32

    (void)in_sizes; (void)n_in; (void)out_size;

    // Opt-in to >48KB dynamic smem (idempotent; host-side, capture-safe)
    cudaFuncSetAttribute(gemm_tf32_kernel,
                         cudaFuncAttributeMaxDynamicSharedMemorySize, SMEM_BYTES);

    // 1) out = bias  AND  g_h = features @ weights (fused)
    const int gemm_blocks = (N_NODES + BM - 1) / BM;  // 782
    gemm_tf32_kernel<<<gemm_blocks, 256, SMEM_BYTES>>>(features, weights, bias, out);

    // 2) out[dst] += w * g_h[src]  (vector L2 reductions, 32 edges/warp)
    const int scatter_warps  = N_EDGES / 32;          // 20000
    const int scatter_blocks = scatter_warps / 8;     // 2500 (256 thr = 8 warps)
    scatter_kernel<<<scatter_blocks, 256>>>(edge_src, edge_dst, edge_w, out);
}

// round 5
// speedup vs baseline: 1.5192x; 1.1906x over previous
#include <cuda_runtime.h>
#include <cuda_fp16.h>
#include <cstdint>

#define N_NODES 100000
#define D_IN    512
#define D_OUT   128
#define N_EDGES 640000

#define BM  128
#define BK  32                  // k per iter (halfs)
#define NIT (D_IN / BK)         // 16

// Scratch (static device arrays: allocation-free)
__device__ __align__(16) float  g_h [(size_t)N_NODES * D_OUT];  // h = X @ W
__device__ __align__(16) __half g_Bt[(size_t)D_OUT   * D_IN ];  // W^T as fp16

// ---------------------------------------------------------------------------
// helpers
// ---------------------------------------------------------------------------
__device__ __forceinline__ void cp16(uint32_t saddr, const void* g) {
    asm volatile("cp.async.cg.shared.global [%0], [%1], 16;" :: "r"(saddr), "l"(g));
}
__device__ __forceinline__ uint32_t pack_half2(float lo, float hi) {
    uint32_t u;
    asm("cvt.rn.f16x2.f32 %0, %1, %2;" : "=r"(u) : "f"(hi), "f"(lo));
    return u;
}
// XOR-swizzled tile offset: 64B rows (32 halfs), 16B chunks, conflict-free for
// STS.128 fill and ldmatrix reads.  kc = k/8 (0..3).
__device__ __forceinline__ uint32_t soff(int row, int kc) {
    return (uint32_t)(row * 64 + ((kc ^ ((row >> 1) & 3)) << 4));
}
#define LDM_X4(r, a) \
    asm volatile("ldmatrix.sync.aligned.m8n8.x4.shared.b16 {%0,%1,%2,%3}, [%4];" \
        : "=r"((r)[0]), "=r"((r)[1]), "=r"((r)[2]), "=r"((r)[3]) : "r"(a))
#define LDM_X2(r, a) \
    asm volatile("ldmatrix.sync.aligned.m8n8.x2.shared.b16 {%0,%1}, [%2];" \
        : "=r"((r)[0]), "=r"((r)[1]) : "r"(a))

__device__ __forceinline__ void mma16816(float c[4], const uint32_t a[4], const uint32_t b[2]) {
    asm volatile(
        "mma.sync.aligned.m16n8k16.row.col.f32.f16.f16.f32 "
        "{%0,%1,%2,%3}, {%4,%5,%6,%7}, {%8,%9}, {%0,%1,%2,%3};"
        : "+f"(c[0]), "+f"(c[1]), "+f"(c[2]), "+f"(c[3])
        : "r"(a[0]), "r"(a[1]), "r"(a[2]), "r"(a[3]), "r"(b[0]), "r"(b[1]));
}

// ---------------------------------------------------------------------------
// Kernel 0: g_Bt[n][k] = half(W[k][n])   (tiny; 64 blocks)
// ---------------------------------------------------------------------------
__global__ void transposeW_kernel(const float* __restrict__ W) {
    __shared__ float tile[32][33];
    const int k0 = (blockIdx.x >> 2) * 32;
    const int n0 = (blockIdx.x & 3) * 32;
    const int r = threadIdx.x >> 5, c = threadIdx.x & 31;
#pragma unroll
    for (int i = 0; i < 32; i += 8)
        tile[r + i][c] = W[(size_t)(k0 + r + i) * D_OUT + n0 + c];
    __syncthreads();
#pragma unroll
    for (int i = 0; i < 32; i += 8)
        g_Bt[(size_t)(n0 + r + i) * D_IN + k0 + c] = __float2half_rn(tile[c][r + i]);
}

// ---------------------------------------------------------------------------
// Kernel 1: fused [out = bias] + [g_h = X @ W]  (fp16 mma.m16n8k16, ldmatrix,
// double-buffered: A reg-prefetch LDG->cvt->STS, B cp.async; 1 sync/iter)
// ---------------------------------------------------------------------------
__global__ __launch_bounds__(256, 2)
void gemm_fp16_kernel(const float* __restrict__ A,    // [N_NODES, 512] f32
                      const float* __restrict__ bias, // [128]
                      float* __restrict__ out) {      // [N_NODES, 128]
    // smem: A stages [2][8KB], B stages [2][8KB]
    __shared__ __align__(16) uint8_t smem[4 * 8192];
    const uint32_t smb = (uint32_t)__cvta_generic_to_shared(smem);
    const uint32_t sA0 = smb;           // + stage*8192
    const uint32_t sB0 = smb + 16384;   // + stage*8192

    const int t = threadIdx.x, warp = t >> 5, lane = t & 31;
    const int wm = (warp >> 2) * 64;        // 0 or 64
    const int wn = (warp & 3) * 32;         // 0,32,64,96
    const int blockRow = blockIdx.x * BM;

    // ---- per-thread fill geometry: 2 chunks (rows r, r+64), same kc ----
    const int fr  = t >> 2;                 // 0..63
    const int kc  = t & 3;                  // 16B chunk within 64B row
    int gr0 = blockRow + fr;       if (gr0 >= N_NODES) gr0 = N_NODES - 1;
    int gr1 = blockRow + fr + 64;  if (gr1 >= N_NODES) gr1 = N_NODES - 1;
    const float* pA0 = A + (size_t)gr0 * D_IN + kc * 8;
    const float* pA1 = A + (size_t)gr1 * D_IN + kc * 8;
    const __half* pB0 = g_Bt + (size_t)fr * D_IN + kc * 8;
    const __half* pB1 = g_Bt + (size_t)(fr + 64) * D_IN + kc * 8;
    const uint32_t offA0 = soff(fr, kc),      offA1 = soff(fr + 64, kc);

    float4 pf[4];   // A prefetch regs: 2 rows x 8 floats

    // ---- prologue: stage 0 of iter 0 ----
    pf[0] = *(const float4*)(pA0 + 0); pf[1] = *(const float4*)(pA0 + 4);
    pf[2] = *(const float4*)(pA1 + 0); pf[3] = *(const float4*)(pA1 + 4);
    cp16(sB0 + offA0, pB0);
    cp16(sB0 + offA1, pB1);
    asm volatile("cp.async.commit_group;");
    {
        uint32_t h0 = pack_half2(pf[0].x, pf[0].y), h1 = pack_half2(pf[0].z, pf[0].w);
        uint32_t h2 = pack_half2(pf[1].x, pf[1].y), h3 = pack_half2(pf[1].z, pf[1].w);
        asm volatile("st.shared.v4.b32 [%0], {%1,%2,%3,%4};"
                     :: "r"(sA0 + offA0), "r"(h0), "r"(h1), "r"(h2), "r"(h3) : "memory");
        h0 = pack_half2(pf[2].x, pf[2].y); h1 = pack_half2(pf[2].z, pf[2].w);
        h2 = pack_half2(pf[3].x, pf[3].y); h3 = pack_half2(pf[3].z, pf[3].w);
        asm volatile("st.shared.v4.b32 [%0], {%1,%2,%3,%4};"
                     :: "r"(sA0 + offA1), "r"(h0), "r"(h1), "r"(h2), "r"(h3) : "memory");
    }
    // fused bias-init (overlaps cp.async/LDG latency)
    for (int i = t; i < BM * 32; i += 256) {
        int row = blockRow + (i >> 5);
        if (row < N_NODES)
            ((float4*)out)[(size_t)row * 32 + (i & 31)] = ((const float4*)bias)[i & 31];
    }
    asm volatile("cp.async.wait_group 0;");
    __syncthreads();

    float acc[4][4][4] = {};

    for (int it = 0; it < NIT; ++it) {
        const uint32_t aB = sA0 + (uint32_t)((it & 1) << 13);
        const uint32_t bB = sB0 + (uint32_t)((it & 1) << 13);
        const uint32_t aN = sA0 + (uint32_t)(((it & 1) ^ 1) << 13);
        const uint32_t bN = sB0 + (uint32_t)(((it & 1) ^ 1) << 13);

        if (it + 1 < NIT) {
            const int ko = (it + 1) * BK;
            pf[0] = *(const float4*)(pA0 + ko);  pf[1] = *(const float4*)(pA0 + ko + 4);
            pf[2] = *(const float4*)(pA1 + ko);  pf[3] = *(const float4*)(pA1 + ko + 4);
            cp16(bN + offA0, pB0 + ko);
            cp16(bN + offA1, pB1 + ko);
            asm volatile("cp.async.commit_group;");
        }

        // ---- compute on current stage: 2 k-steps of m16n8k16 ----
#pragma unroll
        for (int s = 0; s < 2; s++) {
            uint32_t af[4][4], bf[4][2];
            const int akc = s * 2 + (lane >> 4);            // A k-chunk for this lane
            const int arl = lane & 15;                      // A row-in-16
#pragma unroll
            for (int mi = 0; mi < 4; mi++)
                LDM_X4(af[mi], aB + soff(wm + mi * 16 + arl, akc));
            const int bkc = s * 2 + ((lane >> 3) & 1);
            const int brl = lane & 7;
#pragma unroll
            for (int ni = 0; ni < 4; ni++)
                LDM_X2(bf[ni], bB + soff(wn + ni * 8 + brl, bkc));
#pragma unroll
            for (int mi = 0; mi < 4; mi++)
#pragma unroll
                for (int ni = 0; ni < 4; ni++)
                    mma16816(acc[mi][ni], af[mi], bf[ni]);
        }

        if (it + 1 < NIT) {
            // STS prefetched A into next stage (next stage not read by anyone now)
            uint32_t h0 = pack_half2(pf[0].x, pf[0].y), h1 = pack_half2(pf[0].z, pf[0].w);
            uint32_t h2 = pack_half2(pf[1].x, pf[1].y), h3 = pack_half2(pf[1].z, pf[1].w);
            asm volatile("st.shared.v4.b32 [%0], {%1,%2,%3,%4};"
                         :: "r"(aN + offA0), "r"(h0), "r"(h1), "r"(h2), "r"(h3) : "memory");
            h0 = pack_half2(pf[2].x, pf[2].y); h1 = pack_half2(pf[2].z, pf[2].w);
            h2 = pack_half2(pf[3].x, pf[3].y); h3 = pack_half2(pf[3].z, pf[3].w);
            asm volatile("st.shared.v4.b32 [%0], {%1,%2,%3,%4};"
                         :: "r"(aN + offA1), "r"(h0), "r"(h1), "r"(h2), "r"(h3) : "memory");
            asm volatile("cp.async.wait_group 0;");
            __syncthreads();
        }
    }

    // ---- epilogue: acc -> g_h ----
#pragma unroll
    for (int mi = 0; mi < 4; mi++) {
#pragma unroll
        for (int ni = 0; ni < 4; ni++) {
            int r0 = blockRow + wm + mi * 16 + (lane >> 2);
            int c0 = wn + ni * 8 + (lane & 3) * 2;
            if (r0 < N_NODES) {
                g_h[(size_t)r0 * D_OUT + c0]     = acc[mi][ni][0];
                g_h[(size_t)r0 * D_OUT + c0 + 1] = acc[mi][ni][1];
            }
            if (r0 + 8 < N_NODES) {
                g_h[(size_t)(r0 + 8) * D_OUT + c0]     = acc[mi][ni][2];
                g_h[(size_t)(r0 + 8) * D_OUT + c0 + 1] = acc[mi][ni][3];
            }
        }
    }
}

// ---------------------------------------------------------------------------
// Kernel 2: warp-batched edge scatter (at ~84% of LTS roofline; unchanged)
// ---------------------------------------------------------------------------
__global__ void scatter_kernel(const int* __restrict__ src,
                               const int* __restrict__ dst,
                               const float* __restrict__ ew,
                               float* __restrict__ out) {
    const int lane = threadIdx.x & 31;
    const int w = (blockIdx.x * blockDim.x + threadIdx.x) >> 5;
    const int base = w * 32;
    if (base >= N_EDGES) return;

    const int   s  = src[base + lane];
    const int   d  = dst[base + lane];
    const float wt = ew[base + lane];

#pragma unroll 4
    for (int i = 0; i < 32; i++) {
        int   si = __shfl_sync(0xffffffffu, s,  i);
        int   di = __shfl_sync(0xffffffffu, d,  i);
        float wi = __shfl_sync(0xffffffffu, wt, i);
        float4 v = __ldg((const float4*)(g_h + (size_t)si * D_OUT) + lane);
        v.x *= wi; v.y *= wi; v.z *= wi; v.w *= wi;
        float* p = out + (size_t)di * D_OUT + lane * 4;
        asm volatile("red.global.add.v4.f32 [%0], {%1,%2,%3,%4};"
                     :: "l"(p), "f"(v.x), "f"(v.y), "f"(v.z), "f"(v.w)
                     : "memory");
    }
}

// ---------------------------------------------------------------------------
extern "C" void kernel_launch(void* const* d_in, const int* in_sizes, int n_in,
                              void* d_out, int out_size) {
    const float* features = (const float*)d_in[0];  // [100000, 512] f32
    const int*   edge_src = (const int*)d_in[1];    // [640000] int32 (JAX x64 off)
    const int*   edge_dst = (const int*)d_in[2];    // [640000] int32
    const float* edge_w   = (const float*)d_in[3];  // [640000] f32
    const float* weights  = (const float*)d_in[4];  // [512, 128] f32
    const float* bias     = (const float*)d_in[5];  // [128] f32
    float* out = (float*)d_out;                     // [100000, 128] f32

    (void)in_sizes; (void)n_in; (void)out_size;

    // 0) W^T (fp16) into g_Bt
    transposeW_kernel<<<64, 256>>>(weights);

    // 1) out = bias  AND  g_h = X @ W  (fp16 tensor cores)
    const int gemm_blocks = (N_NODES + BM - 1) / BM;  // 782
    gemm_fp16_kernel<<<gemm_blocks, 256>>>(features, bias, out);

    // 2) out[dst] += w * g_h[src]
    scatter_kernel<<<N_EDGES / 32 / 8, 256>>>(edge_src, edge_dst, edge_w, out);
}

// round 6
// speedup vs baseline: 1.5904x; 1.0469x over previous
#include <cuda_runtime.h>
#include <cuda_fp16.h>
#include <cstdint>

#define N_NODES 100000
#define D_IN    512
#define D_OUT   128
#define N_EDGES 640000

#define BM  128
#define BK  32                  // k per iter (halfs)
#define NIT (D_IN / BK)         // 16

// Scratch (static device arrays: allocation-free)
__device__ __align__(16) __half g_h [(size_t)N_NODES * D_OUT];  // h = X @ W (fp16)
__device__ __align__(16) __half g_Bt[(size_t)D_OUT   * D_IN ];  // W^T as fp16

// ---------------------------------------------------------------------------
// helpers
// ---------------------------------------------------------------------------
__device__ __forceinline__ void cp16(uint32_t saddr, const void* g) {
    asm volatile("cp.async.cg.shared.global [%0], [%1], 16;" :: "r"(saddr), "l"(g));
}
__device__ __forceinline__ uint32_t pack_half2(float lo, float hi) {
    uint32_t u;
    asm("cvt.rn.f16x2.f32 %0, %1, %2;" : "=r"(u) : "f"(hi), "f"(lo));
    return u;
}
// XOR-swizzled tile offset: 64B rows (32 halfs), 16B chunks, conflict-free for
// STS.128 fill and ldmatrix reads.  kc = k/8 (0..3).
__device__ __forceinline__ uint32_t soff(int row, int kc) {
    return (uint32_t)(row * 64 + ((kc ^ ((row >> 1) & 3)) << 4));
}
#define LDM_X4(r, a) \
    asm volatile("ldmatrix.sync.aligned.m8n8.x4.shared.b16 {%0,%1,%2,%3}, [%4];" \
        : "=r"((r)[0]), "=r"((r)[1]), "=r"((r)[2]), "=r"((r)[3]) : "r"(a))
#define LDM_X2(r, a) \
    asm volatile("ldmatrix.sync.aligned.m8n8.x2.shared.b16 {%0,%1}, [%2];" \
        : "=r"((r)[0]), "=r"((r)[1]) : "r"(a))

__device__ __forceinline__ void mma16816(float c[4], const uint32_t a[4], const uint32_t b[2]) {
    asm volatile(
        "mma.sync.aligned.m16n8k16.row.col.f32.f16.f16.f32 "
        "{%0,%1,%2,%3}, {%4,%5,%6,%7}, {%8,%9}, {%0,%1,%2,%3};"
        : "+f"(c[0]), "+f"(c[1]), "+f"(c[2]), "+f"(c[3])
        : "r"(a[0]), "r"(a[1]), "r"(a[2]), "r"(a[3]), "r"(b[0]), "r"(b[1]));
}

// ---------------------------------------------------------------------------
// Kernel 0: g_Bt[n][k] = half(W[k][n])   (tiny; 64 blocks)
// ---------------------------------------------------------------------------
__global__ void transposeW_kernel(const float* __restrict__ W) {
    __shared__ float tile[32][33];
    const int k0 = (blockIdx.x >> 2) * 32;
    const int n0 = (blockIdx.x & 3) * 32;
    const int r = threadIdx.x >> 5, c = threadIdx.x & 31;
#pragma unroll
    for (int i = 0; i < 32; i += 8)
        tile[r + i][c] = W[(size_t)(k0 + r + i) * D_OUT + n0 + c];
    __syncthreads();
#pragma unroll
    for (int i = 0; i < 32; i += 8)
        g_Bt[(size_t)(n0 + r + i) * D_IN + k0 + c] = __float2half_rn(tile[c][r + i]);
}

// ---------------------------------------------------------------------------
// Kernel 1: fused [out = bias] + [g_h = X @ W]  (fp16 mma.m16n8k16, ldmatrix,
// double-buffered: A reg-prefetch LDG->cvt->STS, B cp.async; 1 sync/iter)
// ---------------------------------------------------------------------------
__global__ __launch_bounds__(256, 2)
void gemm_fp16_kernel(const float* __restrict__ A,    // [N_NODES, 512] f32
                      const float* __restrict__ bias, // [128]
                      float* __restrict__ out) {      // [N_NODES, 128]
    // smem: A stages [2][8KB], B stages [2][8KB]
    __shared__ __align__(16) uint8_t smem[4 * 8192];
    const uint32_t smb = (uint32_t)__cvta_generic_to_shared(smem);
    const uint32_t sA0 = smb;           // + stage*8192
    const uint32_t sB0 = smb + 16384;   // + stage*8192

    const int t = threadIdx.x, warp = t >> 5, lane = t & 31;
    const int wm = (warp >> 2) * 64;        // 0 or 64
    const int wn = (warp & 3) * 32;         // 0,32,64,96
    const int blockRow = blockIdx.x * BM;

    // ---- per-thread fill geometry: 2 chunks (rows r, r+64), same kc ----
    const int fr  = t >> 2;                 // 0..63
    const int kc  = t & 3;                  // 16B chunk within 64B row
    int gr0 = blockRow + fr;       if (gr0 >= N_NODES) gr0 = N_NODES - 1;
    int gr1 = blockRow + fr + 64;  if (gr1 >= N_NODES) gr1 = N_NODES - 1;
    const float* pA0 = A + (size_t)gr0 * D_IN + kc * 8;
    const float* pA1 = A + (size_t)gr1 * D_IN + kc * 8;
    const __half* pB0 = g_Bt + (size_t)fr * D_IN + kc * 8;
    const __half* pB1 = g_Bt + (size_t)(fr + 64) * D_IN + kc * 8;
    const uint32_t offA0 = soff(fr, kc),      offA1 = soff(fr + 64, kc);

    float4 pf[4];   // A prefetch regs: 2 rows x 8 floats

    // ---- prologue: stage 0 of iter 0 ----
    pf[0] = *(const float4*)(pA0 + 0); pf[1] = *(const float4*)(pA0 + 4);
    pf[2] = *(const float4*)(pA1 + 0); pf[3] = *(const float4*)(pA1 + 4);
    cp16(sB0 + offA0, pB0);
    cp16(sB0 + offA1, pB1);
    asm volatile("cp.async.commit_group;");
    {
        uint32_t h0 = pack_half2(pf[0].x, pf[0].y), h1 = pack_half2(pf[0].z, pf[0].w);
        uint32_t h2 = pack_half2(pf[1].x, pf[1].y), h3 = pack_half2(pf[1].z, pf[1].w);
        asm volatile("st.shared.v4.b32 [%0], {%1,%2,%3,%4};"
                     :: "r"(sA0 + offA0), "r"(h0), "r"(h1), "r"(h2), "r"(h3) : "memory");
        h0 = pack_half2(pf[2].x, pf[2].y); h1 = pack_half2(pf[2].z, pf[2].w);
        h2 = pack_half2(pf[3].x, pf[3].y); h3 = pack_half2(pf[3].z, pf[3].w);
        asm volatile("st.shared.v4.b32 [%0], {%1,%2,%3,%4};"
                     :: "r"(sA0 + offA1), "r"(h0), "r"(h1), "r"(h2), "r"(h3) : "memory");
    }
    // fused bias-init (overlaps cp.async/LDG latency)
    for (int i = t; i < BM * 32; i += 256) {
        int row = blockRow + (i >> 5);
        if (row < N_NODES)
            ((float4*)out)[(size_t)row * 32 + (i & 31)] = ((const float4*)bias)[i & 31];
    }
    asm volatile("cp.async.wait_group 0;");
    __syncthreads();

    float acc[4][4][4] = {};

    for (int it = 0; it < NIT; ++it) {
        const uint32_t aB = sA0 + (uint32_t)((it & 1) << 13);
        const uint32_t bB = sB0 + (uint32_t)((it & 1) << 13);
        const uint32_t aN = sA0 + (uint32_t)(((it & 1) ^ 1) << 13);
        const uint32_t bN = sB0 + (uint32_t)(((it & 1) ^ 1) << 13);

        if (it + 1 < NIT) {
            const int ko = (it + 1) * BK;
            pf[0] = *(const float4*)(pA0 + ko);  pf[1] = *(const float4*)(pA0 + ko + 4);
            pf[2] = *(const float4*)(pA1 + ko);  pf[3] = *(const float4*)(pA1 + ko + 4);
            cp16(bN + offA0, pB0 + ko);
            cp16(bN + offA1, pB1 + ko);
            asm volatile("cp.async.commit_group;");
        }

        // ---- compute on current stage: 2 k-steps of m16n8k16 ----
#pragma unroll
        for (int s = 0; s < 2; s++) {
            uint32_t af[4][4], bf[4][2];
            const int akc = s * 2 + (lane >> 4);            // A k-chunk for this lane
            const int arl = lane & 15;                      // A row-in-16
#pragma unroll
            for (int mi = 0; mi < 4; mi++)
                LDM_X4(af[mi], aB + soff(wm + mi * 16 + arl, akc));
            const int bkc = s * 2 + ((lane >> 3) & 1);
            const int brl = lane & 7;
#pragma unroll
            for (int ni = 0; ni < 4; ni++)
                LDM_X2(bf[ni], bB + soff(wn + ni * 8 + brl, bkc));
#pragma unroll
            for (int mi = 0; mi < 4; mi++)
#pragma unroll
                for (int ni = 0; ni < 4; ni++)
                    mma16816(acc[mi][ni], af[mi], bf[ni]);
        }

        if (it + 1 < NIT) {
            // STS prefetched A into next stage (next stage not read by anyone now)
            uint32_t h0 = pack_half2(pf[0].x, pf[0].y), h1 = pack_half2(pf[0].z, pf[0].w);
            uint32_t h2 = pack_half2(pf[1].x, pf[1].y), h3 = pack_half2(pf[1].z, pf[1].w);
            asm volatile("st.shared.v4.b32 [%0], {%1,%2,%3,%4};"
                         :: "r"(aN + offA0), "r"(h0), "r"(h1), "r"(h2), "r"(h3) : "memory");
            h0 = pack_half2(pf[2].x, pf[2].y); h1 = pack_half2(pf[2].z, pf[2].w);
            h2 = pack_half2(pf[3].x, pf[3].y); h3 = pack_half2(pf[3].z, pf[3].w);
            asm volatile("st.shared.v4.b32 [%0], {%1,%2,%3,%4};"
                         :: "r"(aN + offA1), "r"(h0), "r"(h1), "r"(h2), "r"(h3) : "memory");
            asm volatile("cp.async.wait_group 0;");
            __syncthreads();
        }
    }

    // ---- epilogue: acc -> g_h (packed fp16; c0 is even so 4B stores align) ----
#pragma unroll
    for (int mi = 0; mi < 4; mi++) {
#pragma unroll
        for (int ni = 0; ni < 4; ni++) {
            int r0 = blockRow + wm + mi * 16 + (lane >> 2);
            int c0 = wn + ni * 8 + (lane & 3) * 2;
            if (r0 < N_NODES)
                *(uint32_t*)(g_h + (size_t)r0 * D_OUT + c0) =
                    pack_half2(acc[mi][ni][0], acc[mi][ni][1]);
            if (r0 + 8 < N_NODES)
                *(uint32_t*)(g_h + (size_t)(r0 + 8) * D_OUT + c0) =
                    pack_half2(acc[mi][ni][2], acc[mi][ni][3]);
        }
    }
}

// ---------------------------------------------------------------------------
// Kernel 2: warp-batched edge scatter. fp16 gather (8B/lane) halves gather
// traffic; reduce stays fp32 red.v4 into out.
// ---------------------------------------------------------------------------
__global__ void scatter_kernel(const int* __restrict__ src,
                               const int* __restrict__ dst,
                               const float* __restrict__ ew,
                               float* __restrict__ out) {
    const int lane = threadIdx.x & 31;
    const int w = (blockIdx.x * blockDim.x + threadIdx.x) >> 5;
    const int base = w * 32;
    if (base >= N_EDGES) return;

    const int   s  = src[base + lane];
    const int   d  = dst[base + lane];
    const float wt = ew[base + lane];

#pragma unroll 4
    for (int i = 0; i < 32; i++) {
        int   si = __shfl_sync(0xffffffffu, s,  i);
        int   di = __shfl_sync(0xffffffffu, d,  i);
        float wi = __shfl_sync(0xffffffffu, wt, i);
        uint2 raw = __ldg((const uint2*)(g_h + (size_t)si * D_OUT) + lane);
        float2 f01 = __half22float2(*(__half2*)&raw.x);
        float2 f23 = __half22float2(*(__half2*)&raw.y);
        float4 v = make_float4(f01.x * wi, f01.y * wi, f23.x * wi, f23.y * wi);
        float* p = out + (size_t)di * D_OUT + lane * 4;
        asm volatile("red.global.add.v4.f32 [%0], {%1,%2,%3,%4};"
                     :: "l"(p), "f"(v.x), "f"(v.y), "f"(v.z), "f"(v.w)
                     : "memory");
    }
}

// ---------------------------------------------------------------------------
extern "C" void kernel_launch(void* const* d_in, const int* in_sizes, int n_in,
                              void* d_out, int out_size) {
    const float* features = (const float*)d_in[0];  // [100000, 512] f32
    const int*   edge_src = (const int*)d_in[1];    // [640000] int32 (JAX x64 off)
    const int*   edge_dst = (const int*)d_in[2];    // [640000] int32
    const float* edge_w   = (const float*)d_in[3];  // [640000] f32
    const float* weights  = (const float*)d_in[4];  // [512, 128] f32
    const float* bias     = (const float*)d_in[5];  // [128] f32
    float* out = (float*)d_out;                     // [100000, 128] f32

    (void)in_sizes; (void)n_in; (void)out_size;

    // 0) W^T (fp16) into g_Bt
    transposeW_kernel<<<64, 256>>>(weights);

    // 1) out = bias  AND  g_h = X @ W  (fp16 tensor cores)
    const int gemm_blocks = (N_NODES + BM - 1) / BM;  // 782
    gemm_fp16_kernel<<<gemm_blocks, 256>>>(features, bias, out);

    // 2) out[dst] += w * g_h[src]  (fp16 gather, fp32 reduce)
    scatter_kernel<<<N_EDGES / 32 / 8, 256>>>(edge_src, edge_dst, edge_w, out);
}

// round 7
// speedup vs baseline: 1.6187x; 1.0178x over previous
#include <cuda_runtime.h>
#include <cuda_fp16.h>
#include <cstdint>

#define N_NODES 100000
#define D_IN    512
#define D_OUT   128
#define N_EDGES 640000

#define BM  128
#define BK  32
#define NIT (D_IN / BK)         // 16

// Scratch (static device arrays: allocation-free)
__device__ __align__(16) __half g_h    [(size_t)N_NODES * D_OUT]; // h = X @ W (fp16)
__device__ __align__(16) __half g_Bt   [(size_t)D_OUT   * D_IN ]; // W^T as fp16
__device__ int  g_count [N_NODES];
__device__ int  g_offset[N_NODES];
__device__ int  g_cursor[N_NODES];
__device__ int  g_total;
__device__ __align__(8) int2 g_edges[N_EDGES];   // (src, w-bits) bucketed by dst

// ---------------------------------------------------------------------------
// helpers
// ---------------------------------------------------------------------------
__device__ __forceinline__ void cp16(uint32_t saddr, const void* g) {
    asm volatile("cp.async.cg.shared.global [%0], [%1], 16;" :: "r"(saddr), "l"(g));
}
__device__ __forceinline__ uint32_t pack_half2(float lo, float hi) {
    uint32_t u;
    asm("cvt.rn.f16x2.f32 %0, %1, %2;" : "=r"(u) : "f"(hi), "f"(lo));
    return u;
}
__device__ __forceinline__ uint32_t soff(int row, int kc) {
    return (uint32_t)(row * 64 + ((kc ^ ((row >> 1) & 3)) << 4));
}
#define LDM_X4(r, a) \
    asm volatile("ldmatrix.sync.aligned.m8n8.x4.shared.b16 {%0,%1,%2,%3}, [%4];" \
        : "=r"((r)[0]), "=r"((r)[1]), "=r"((r)[2]), "=r"((r)[3]) : "r"(a))
#define LDM_X2(r, a) \
    asm volatile("ldmatrix.sync.aligned.m8n8.x2.shared.b16 {%0,%1}, [%2];" \
        : "=r"((r)[0]), "=r"((r)[1]) : "r"(a))

__device__ __forceinline__ void mma16816(float c[4], const uint32_t a[4], const uint32_t b[2]) {
    asm volatile(
        "mma.sync.aligned.m16n8k16.row.col.f32.f16.f16.f32 "
        "{%0,%1,%2,%3}, {%4,%5,%6,%7}, {%8,%9}, {%0,%1,%2,%3};"
        : "+f"(c[0]), "+f"(c[1]), "+f"(c[2]), "+f"(c[3])
        : "r"(a[0]), "r"(a[1]), "r"(a[2]), "r"(a[3]), "r"(b[0]), "r"(b[1]));
}

// ---------------------------------------------------------------------------
// Kernel 0: g_Bt[n][k] = half(W[k][n])
// ---------------------------------------------------------------------------
__global__ void transposeW_kernel(const float* __restrict__ W) {
    __shared__ float tile[32][33];
    const int k0 = (blockIdx.x >> 2) * 32;
    const int n0 = (blockIdx.x & 3) * 32;
    const int r = threadIdx.x >> 5, c = threadIdx.x & 31;
#pragma unroll
    for (int i = 0; i < 32; i += 8)
        tile[r + i][c] = W[(size_t)(k0 + r + i) * D_OUT + n0 + c];
    __syncthreads();
#pragma unroll
    for (int i = 0; i < 32; i += 8)
        g_Bt[(size_t)(n0 + r + i) * D_IN + k0 + c] = __float2half_rn(tile[c][r + i]);
}

// ---------------------------------------------------------------------------
// CSR-bucket build (replayed every launch: arrays re-zeroed here)
// ---------------------------------------------------------------------------
__global__ void zero_kernel() {
    int i = blockIdx.x * blockDim.x + threadIdx.x;
    if (i < N_NODES) g_count[i] = 0;
    if (i == 0) g_total = 0;
}

__global__ void hist_kernel(const int* __restrict__ dst) {
    int e = blockIdx.x * blockDim.x + threadIdx.x;
    if (e < N_EDGES) atomicAdd(&g_count[dst[e]], 1);
}

__global__ void offsets_kernel() {
    int n = blockIdx.x * blockDim.x + threadIdx.x;
    int lane = threadIdx.x & 31;
    int v = (n < N_NODES) ? g_count[n] : 0;
    int s = v;
#pragma unroll
    for (int d = 1; d < 32; d <<= 1) {
        int u = __shfl_up_sync(0xffffffffu, s, d);
        if (lane >= d) s += u;
    }
    int ex = s - v;
    int total = __shfl_sync(0xffffffffu, s, 31);
    int base = 0;
    if (lane == 31) base = atomicAdd(&g_total, total);
    base = __shfl_sync(0xffffffffu, base, 31);
    if (n < N_NODES) { g_offset[n] = base + ex; g_cursor[n] = base + ex; }
}

__global__ void reorder_kernel(const int* __restrict__ src,
                               const int* __restrict__ dst,
                               const float* __restrict__ ew) {
    int e = blockIdx.x * blockDim.x + threadIdx.x;
    if (e >= N_EDGES) return;
    int pos = atomicAdd(&g_cursor[dst[e]], 1);
    g_edges[pos] = make_int2(src[e], __float_as_int(ew[e]));
}

// ---------------------------------------------------------------------------
// Kernel: fp16 GEMM  g_h = X @ W  (mma.m16n8k16, ldmatrix, double-buffered)
// ---------------------------------------------------------------------------
__global__ __launch_bounds__(256, 2)
void gemm_fp16_kernel(const float* __restrict__ A) {   // [N_NODES, 512] f32
    __shared__ __align__(16) uint8_t smem[4 * 8192];
    const uint32_t smb = (uint32_t)__cvta_generic_to_shared(smem);
    const uint32_t sA0 = smb;
    const uint32_t sB0 = smb + 16384;

    const int t = threadIdx.x, warp = t >> 5, lane = t & 31;
    const int wm = (warp >> 2) * 64;
    const int wn = (warp & 3) * 32;
    const int blockRow = blockIdx.x * BM;

    const int fr  = t >> 2;
    const int kc  = t & 3;
    int gr0 = blockRow + fr;       if (gr0 >= N_NODES) gr0 = N_NODES - 1;
    int gr1 = blockRow + fr + 64;  if (gr1 >= N_NODES) gr1 = N_NODES - 1;
    const float* pA0 = A + (size_t)gr0 * D_IN + kc * 8;
    const float* pA1 = A + (size_t)gr1 * D_IN + kc * 8;
    const __half* pB0 = g_Bt + (size_t)fr * D_IN + kc * 8;
    const __half* pB1 = g_Bt + (size_t)(fr + 64) * D_IN + kc * 8;
    const uint32_t offA0 = soff(fr, kc), offA1 = soff(fr + 64, kc);

    float4 pf[4];

    pf[0] = *(const float4*)(pA0 + 0); pf[1] = *(const float4*)(pA0 + 4);
    pf[2] = *(const float4*)(pA1 + 0); pf[3] = *(const float4*)(pA1 + 4);
    cp16(sB0 + offA0, pB0);
    cp16(sB0 + offA1, pB1);
    asm volatile("cp.async.commit_group;");
    {
        uint32_t h0 = pack_half2(pf[0].x, pf[0].y), h1 = pack_half2(pf[0].z, pf[0].w);
        uint32_t h2 = pack_half2(pf[1].x, pf[1].y), h3 = pack_half2(pf[1].z, pf[1].w);
        asm volatile("st.shared.v4.b32 [%0], {%1,%2,%3,%4};"
                     :: "r"(sA0 + offA0), "r"(h0), "r"(h1), "r"(h2), "r"(h3) : "memory");
        h0 = pack_half2(pf[2].x, pf[2].y); h1 = pack_half2(pf[2].z, pf[2].w);
        h2 = pack_half2(pf[3].x, pf[3].y); h3 = pack_half2(pf[3].z, pf[3].w);
        asm volatile("st.shared.v4.b32 [%0], {%1,%2,%3,%4};"
                     :: "r"(sA0 + offA1), "r"(h0), "r"(h1), "r"(h2), "r"(h3) : "memory");
    }
    asm volatile("cp.async.wait_group 0;");
    __syncthreads();

    float acc[4][4][4] = {};

    for (int it = 0; it < NIT; ++it) {
        const uint32_t aB = sA0 + (uint32_t)((it & 1) << 13);
        const uint32_t bB = sB0 + (uint32_t)((it & 1) << 13);
        const uint32_t aN = sA0 + (uint32_t)(((it & 1) ^ 1) << 13);
        const uint32_t bN = sB0 + (uint32_t)(((it & 1) ^ 1) << 13);

        if (it + 1 < NIT) {
            const int ko = (it + 1) * BK;
            pf[0] = *(const float4*)(pA0 + ko);  pf[1] = *(const float4*)(pA0 + ko + 4);
            pf[2] = *(const float4*)(pA1 + ko);  pf[3] = *(const float4*)(pA1 + ko + 4);
            cp16(bN + offA0, pB0 + ko);
            cp16(bN + offA1, pB1 + ko);
            asm volatile("cp.async.commit_group;");
        }

#pragma unroll
        for (int s = 0; s < 2; s++) {
            uint32_t af[4][4], bf[4][2];
            const int akc = s * 2 + (lane >> 4);
            const int arl = lane & 15;
#pragma unroll
            for (int mi = 0; mi < 4; mi++)
                LDM_X4(af[mi], aB + soff(wm + mi * 16 + arl, akc));
            const int bkc = s * 2 + ((lane >> 3) & 1);
            const int brl = lane & 7;
#pragma unroll
            for (int ni = 0; ni < 4; ni++)
                LDM_X2(bf[ni], bB + soff(wn + ni * 8 + brl, bkc));
#pragma unroll
            for (int mi = 0; mi < 4; mi++)
#pragma unroll
                for (int ni = 0; ni < 4; ni++)
                    mma16816(acc[mi][ni], af[mi], bf[ni]);
        }

        if (it + 1 < NIT) {
            uint32_t h0 = pack_half2(pf[0].x, pf[0].y), h1 = pack_half2(pf[0].z, pf[0].w);
            uint32_t h2 = pack_half2(pf[1].x, pf[1].y), h3 = pack_half2(pf[1].z, pf[1].w);
            asm volatile("st.shared.v4.b32 [%0], {%1,%2,%3,%4};"
                         :: "r"(aN + offA0), "r"(h0), "r"(h1), "r"(h2), "r"(h3) : "memory");
            h0 = pack_half2(pf[2].x, pf[2].y); h1 = pack_half2(pf[2].z, pf[2].w);
            h2 = pack_half2(pf[3].x, pf[3].y); h3 = pack_half2(pf[3].z, pf[3].w);
            asm volatile("st.shared.v4.b32 [%0], {%1,%2,%3,%4};"
                         :: "r"(aN + offA1), "r"(h0), "r"(h1), "r"(h2), "r"(h3) : "memory");
            asm volatile("cp.async.wait_group 0;");
            __syncthreads();
        }
    }

#pragma unroll
    for (int mi = 0; mi < 4; mi++) {
#pragma unroll
        for (int ni = 0; ni < 4; ni++) {
            int r0 = blockRow + wm + mi * 16 + (lane >> 2);
            int c0 = wn + ni * 8 + (lane & 3) * 2;
            if (r0 < N_NODES)
                *(uint32_t*)(g_h + (size_t)r0 * D_OUT + c0) =
                    pack_half2(acc[mi][ni][0], acc[mi][ni][1]);
            if (r0 + 8 < N_NODES)
                *(uint32_t*)(g_h + (size_t)(r0 + 8) * D_OUT + c0) =
                    pack_half2(acc[mi][ni][2], acc[mi][ni][3]);
        }
    }
}

// ---------------------------------------------------------------------------
// Aggregate: one warp per node. Edge records batch-loaded 32-wide then
// shfl-broadcast; fp16 gather, fp32 register accumulation; NO atomics.
// ---------------------------------------------------------------------------
__global__ __launch_bounds__(256)
void aggregate_kernel(const float* __restrict__ bias, float* __restrict__ out) {
    const int w = (blockIdx.x * blockDim.x + threadIdx.x) >> 5;
    if (w >= N_NODES) return;
    const int lane = threadIdx.x & 31;
    const int off = g_offset[w];
    const int cnt = g_count[w];

    float a0 = 0.f, a1 = 0.f, a2 = 0.f, a3 = 0.f;

    for (int base = 0; base < cnt; base += 32) {
        const int nb = min(32, cnt - base);
        int2 e = (lane < nb) ? g_edges[off + base + lane] : make_int2(0, 0);
        for (int i = 0; i < nb; i++) {
            int   si = __shfl_sync(0xffffffffu, e.x, i);
            float wi = __int_as_float(__shfl_sync(0xffffffffu, e.y, i));
            uint2 raw = __ldg((const uint2*)(g_h + (size_t)si * D_OUT) + lane);
            float2 f01 = __half22float2(*(__half2*)&raw.x);
            float2 f23 = __half22float2(*(__half2*)&raw.y);
            a0 += wi * f01.x; a1 += wi * f01.y;
            a2 += wi * f23.x; a3 += wi * f23.y;
        }
    }

    float4 bv = ((const float4*)bias)[lane];
    ((float4*)out)[(size_t)w * 32 + lane] =
        make_float4(a0 + bv.x, a1 + bv.y, a2 + bv.z, a3 + bv.w);
}

// ---------------------------------------------------------------------------
extern "C" void kernel_launch(void* const* d_in, const int* in_sizes, int n_in,
                              void* d_out, int out_size) {
    const float* features = (const float*)d_in[0];  // [100000, 512] f32
    const int*   edge_src = (const int*)d_in[1];    // [640000] int32
    const int*   edge_dst = (const int*)d_in[2];    // [640000] int32
    const float* edge_w   = (const float*)d_in[3];  // [640000] f32
    const float* weights  = (const float*)d_in[4];  // [512, 128] f32
    const float* bias     = (const float*)d_in[5];  // [128] f32
    float* out = (float*)d_out;                     // [100000, 128] f32

    (void)in_sizes; (void)n_in; (void)out_size;

    // W^T (fp16)
    transposeW_kernel<<<64, 256>>>(weights);

    // CSR-bucket build
    zero_kernel<<<(N_NODES + 255) / 256, 256>>>();
    hist_kernel<<<(N_EDGES + 255) / 256, 256>>>(edge_dst);
    offsets_kernel<<<(N_NODES + 255) / 256, 256>>>();
    reorder_kernel<<<(N_EDGES + 255) / 256, 256>>>(edge_src, edge_dst, edge_w);

    // g_h = X @ W (fp16 tensor cores)
    gemm_fp16_kernel<<<(N_NODES + BM - 1) / BM, 256>>>(features);

    // out = bias + sum_{e: dst=n} w_e * g_h[src_e]   (atomic-free)
    aggregate_kernel<<<(N_NODES * 32 + 255) / 256, 256>>>(bias, out);
}